// round 10
// baseline (speedup 1.0000x reference)
#include <cuda_runtime.h>
#include <stdint.h>

// ---------------------------------------------------------------------------
// VanDerWallsSurface: scatter point features into a 128^3 voxel grid.
//  out[b,x,y,z] = [max f0, min f1, mean f2] over points whose sphere covers
//  the voxel (within the 5x5x5 neighborhood of round(coords)), else zeros.
//
// R10: TMA bulk stores for the output + offset pruning in the scatter.
//  R8/R9 evidence: write-only sweep stuck at ~2.5TB/s with DRAM=22%,
//  issue=26% — not BW-bound, not issue-bound per ncu; suspect = SM-side
//  store path. R5 (extra 134MB of reads!) was FASTER than the write-only
//  sweeps, pointing away from DRAM and at STG processing.
//  R10: stage 1024 voxels (12KB) per block in smem, emit with ONE
//  cp.async.bulk.global.shared::cta per block — TMA engines own all output
//  stores (chip TMA throughput == LTS cap, path-independent). Scatter only
//  spawns the 93/125 offsets with |o|^2 <= 8 (the rest can never be within
//  r <= 2 of the point: min dist >= |o| - sqrt(3)/2 > 2).
//
//  - Order-preserving uint encodings make 0 the neutral element for all four
//    accumulators -> scratch is a zero-initialized static; the sweep re-zeroes
//    dirty Acc entries and its bitmap words: all-zero across graph replays.
// ---------------------------------------------------------------------------

#define VOL        128
#define NB         4
#define NPTS       4096
#define NPOINTS    (NB * NPTS)            // 16384
#define TOTAL_VOX  (NB * VOL * VOL * VOL) // 8,388,608
#define NLINES     (TOTAL_VOX / 8)        // 1,048,576 (8 Acc per 128B line)
#define NWORDS     (NLINES / 32)          // 32,768 bitmap words
#define TPB        256

// Feasible offsets: |o|^2 <= 8 (93 of 125).
constexpr int nfeas() {
    int n = 0;
    for (int k = 0; k < 125; k++) {
        int ox = k / 25 - 2, oy = (k / 5) % 5 - 2, oz = k % 5 - 2;
        if (ox * ox + oy * oy + oz * oz <= 8) n++;
    }
    return n;
}
#define NFEAS 93
static_assert(nfeas() == NFEAS, "feasible offset count");

struct FeasTable { unsigned char v[NFEAS]; };
constexpr FeasTable makeFeas() {
    FeasTable t{}; int n = 0;
    for (int k = 0; k < 125; k++) {
        int ox = k / 25 - 2, oy = (k / 5) % 5 - 2, oz = k % 5 - 2;
        if (ox * ox + oy * oy + oz * oz <= 8) t.v[n++] = (unsigned char)k;
    }
    return t;
}
__constant__ FeasTable c_feas = makeFeas();

#define NCAND       (NPOINTS * NFEAS)         // 1,523,712 candidates
#define SCAT_BLOCKS ((NCAND + TPB - 1) / TPB) // 5,953

#define VPB          1024                     // voxels per sweep block
#define SWEEP_BLOCKS (TOTAL_VOX / VPB)        // 8,192
#define TILE_BYTES   (VPB * 12)               // 12,288 B output tile

// Interleaved per-voxel accumulator: one 128B cache line covers all four
// fields of 8 z-adjacent voxels. All neutral elements are 0.
struct Acc {
    unsigned int maxk;  // max-key of f0
    unsigned int mink;  // ~min-key of f1 (min via max)
    unsigned int cnt;   // hit count
    float        sum;   // sum of f2
};
__device__ Acc          g_acc[TOTAL_VOX];  // zero-init; kept zero by k_sweep
__device__ unsigned int g_dirty[NWORDS];   // 1 bit per Acc line; cleared by k_sweep

// Order-preserving float -> uint key. For any finite non-NaN f, fkey(f) > 0,
// so 0 is a valid "empty" sentinel for atomicMax accumulation.
__device__ __forceinline__ unsigned int fkey(float f) {
    unsigned int u = __float_as_uint(f);
    return (u & 0x80000000u) ? ~u : (u | 0x80000000u);
}
__device__ __forceinline__ float funkey(unsigned int k) {
    unsigned int u = (k & 0x80000000u) ? (k ^ 0x80000000u) : ~k;
    return __uint_as_float(u);
}

__device__ __forceinline__ unsigned int smem_u32(const void* p) {
    unsigned int a;
    asm("{ .reg .u64 t; cvta.to.shared.u64 t, %1; cvt.u32.u64 %0, t; }"
        : "=r"(a) : "l"(p));
    return a;
}

// Kernel A: one thread per (point, feasible-offset) candidate; hits do 4
// atomics into the voxel's interleaved Acc plus one dirty-bit atomicOr.
__global__ void __launch_bounds__(TPB) k_scatter(
    const float4* __restrict__ cr,     // (B*N) x [cx, cy, cz, r]
    const float*  __restrict__ feat)   // (B*N) x 3
{
    int t = blockIdx.x * TPB + threadIdx.x;    // candidate id
    if (t >= NCAND) return;
    int j  = t % NFEAS;
    int pn = t / NFEAS;                        // linear point id
    int k  = c_feas.v[j];

    float4 c = __ldg(cr + pn);  // 93 consecutive threads share -> L1 broadcast

    int ox = k / 25 - 2;
    int oy = (k / 5) % 5 - 2;
    int oz = k % 5 - 2;

    // jnp.round == round-half-to-even == rn conversions
    int vx = __float2int_rn(c.x) + ox;
    int vy = __float2int_rn(c.y) + oy;
    int vz = __float2int_rn(c.z) + oz;

    // Exact IEEE ops, left-to-right sum, matching the reference (no FMA
    // contraction that could flip sphere-boundary membership).
    float dx = __fsub_rn((float)vx, c.x);
    float dy = __fsub_rn((float)vy, c.y);
    float dz = __fsub_rn((float)vz, c.z);
    float d2 = __fadd_rn(__fadd_rn(__fmul_rn(dx, dx), __fmul_rn(dy, dy)),
                         __fmul_rn(dz, dz));

    float rr = __fdiv_rn(rintf(__fmul_rn(c.w, 1000.0f)), 1000.0f);
    float r2 = __fmul_rn(rr, rr);

    bool ok = (d2 <= r2)
            && ((unsigned)vx < VOL) && ((unsigned)vy < VOL) && ((unsigned)vz < VOL);
    if (!ok) return;

    unsigned e = (unsigned)((pn >> 12) * (VOL * VOL * VOL)
                            + ((vx * VOL + vy) * VOL + vz));

    const float* fp = feat + (size_t)pn * 3;
    float f0 = __ldg(fp + 0);
    float f1 = __ldg(fp + 1);
    float f2 = __ldg(fp + 2);

    Acc* a = &g_acc[e];
    atomicMax(&a->maxk, fkey(f0));
    atomicMax(&a->mink, ~fkey(f1));     // min via max of complemented key
    atomicAdd(&a->cnt, 1u);
    atomicAdd(&a->sum, f2);

    unsigned line = e >> 3;             // 8 Acc per 128B line
    atomicOr(&g_dirty[line >> 5], 1u << (line & 31u));
}

// Kernel B: block b covers voxels [b*1024, b*1024+1024) = 128 Acc lines =
// bitmap words [b*4, b*4+4). Each thread decodes 4 voxels (strided by 256)
// into a 12KB smem tile; then ONE cp.async.bulk ships the tile to d_out via
// the TMA engine (no SM-side STG at all). Dirty lines are re-zeroed; the
// block clears its own bitmap words after the barrier.
__global__ void __launch_bounds__(TPB) k_sweep(float* __restrict__ out)
{
    __shared__ __align__(16) float s[VPB * 3];     // 12KB output tile

    unsigned b    = blockIdx.x;
    unsigned base = b * VPB;
    unsigned wbit[4];

#pragma unroll
    for (int j = 0; j < 4; j++) {
        unsigned w = g_dirty[b * 4 + j];           // block-uniform broadcast
        wbit[j] = w;
        unsigned l = threadIdx.x + j * TPB;        // local voxel in [j*256,(j+1)*256)
        unsigned e = base + l;                     // global voxel

        float v0 = 0.0f, v1 = 0.0f, v2 = 0.0f;
        if ((w >> ((l >> 3) & 31u)) & 1u) {        // this line dirty
            uint4* ap = reinterpret_cast<uint4*>(g_acc) + e;  // lane-dense
            uint4 a = *ap;
            if (a.z != 0u) {                       // cnt != 0
                v0 = funkey(a.x);
                v1 = funkey(~a.y);
                v2 = __fdiv_rn(__uint_as_float(a.w), (float)a.z);
                *ap = make_uint4(0u, 0u, 0u, 0u);  // self-clean for next call
            }
        }
        s[l * 3 + 0] = v0;                         // gcd(3,32)=1: conflict-free
        s[l * 3 + 1] = v1;
        s[l * 3 + 2] = v2;
    }
    __syncthreads();

    // Clear this block's bitmap words (exclusive ownership; all reads of the
    // words happened before the barrier).
    if (threadIdx.x < 4 && wbit[threadIdx.x] != 0u)
        g_dirty[b * 4 + threadIdx.x] = 0u;

    // Single TMA bulk store: smem tile -> d_out[b*3072 .. +3072 floats).
    if (threadIdx.x == 0) {
        asm volatile("fence.proxy.async.shared::cta;" ::: "memory");
        unsigned saddr = smem_u32(s);
        const float* g = out + (size_t)b * (VPB * 3);
        asm volatile(
            "cp.async.bulk.global.shared::cta.bulk_group [%0], [%1], %2;"
            :: "l"(g), "r"(saddr), "r"(TILE_BYTES) : "memory");
        asm volatile("cp.async.bulk.commit_group;" ::: "memory");
        asm volatile("cp.async.bulk.wait_group 0;" ::: "memory");
    }
}

extern "C" void kernel_launch(void* const* d_in, const int* in_sizes, int n_in,
                              void* d_out, int out_size)
{
    const float4* cr   = (const float4*)d_in[0];  // coordinates_radii (B,N,4)
    const float*  feat = (const float*)d_in[1];   // features (B,N,3)
    float*        out  = (float*)d_out;           // (B,128,128,128,3) f32

    k_scatter<<<SCAT_BLOCKS, TPB>>>(cr, feat);
    k_sweep<<<SWEEP_BLOCKS, TPB>>>(out);
}

// round 11
// speedup vs baseline: 1.7686x; 1.7686x over previous
#include <cuda_runtime.h>
#include <stdint.h>

// ---------------------------------------------------------------------------
// VanDerWallsSurface: scatter point features into a 128^3 voxel grid.
//  out[b,x,y,z] = [max f0, min f1, mean f2] over points whose sphere covers
//  the voxel (within the 5x5x5 neighborhood of round(coords)), else zeros.
//
// R11: R8 structure + less block churn + write-back stores.
//  R10 evidence (FAILED, reverted): per-block TMA wait serialized blocks; but
//  it proved the output write rate (~2.5TB/s) is path-independent (scalar
//  STG == float4 STG == TMA). All pipes <30% -> residual suspects are CTA
//  launch/drain churn (32768 x ~1us blocks) and __stcs forcing synchronous
//  DRAM writeback instead of parking dirty lines in the 126MB L2.
//  R11: sweep = 4096 blocks x 8 bitmap-words (grid-stride, store-only loop
//  iterations overlap), plain write-back stores (L2 absorbs the output and
//  flushes lazily, incl. under the next replay's latency-bound scatter).
//  Scatter is bit-identical to R9.
//
//  - Order-preserving uint encodings make 0 the neutral element for all four
//    accumulators -> scratch is a zero-initialized static; the sweep re-zeroes
//    dirty Acc entries and its bitmap words: all-zero across graph replays.
// ---------------------------------------------------------------------------

#define VOL        128
#define NB         4
#define NPTS       4096
#define NPOINTS    (NB * NPTS)            // 16384
#define KOFF       125                    // 5x5x5 offsets
#define NCAND      (NPOINTS * KOFF)       // 2,048,000 candidates
#define TOTAL_VOX  (NB * VOL * VOL * VOL) // 8,388,608
#define NLINES     (TOTAL_VOX / 8)        // 1,048,576 (8 Acc per 128B line)
#define NWORDS     (NLINES / 32)          // 32,768 bitmap words
#define TPB        256

#define SCAT_BLOCKS  (NCAND / TPB)        // 8,000
#define WPB          8                    // bitmap words per sweep block
#define SWEEP_BLOCKS (NWORDS / WPB)       // 4,096

// Interleaved per-voxel accumulator: one 128B cache line covers all four
// fields of 8 z-adjacent voxels. All neutral elements are 0.
struct Acc {
    unsigned int maxk;  // max-key of f0
    unsigned int mink;  // ~min-key of f1 (min via max)
    unsigned int cnt;   // hit count
    float        sum;   // sum of f2
};
__device__ Acc          g_acc[TOTAL_VOX];  // zero-init; kept zero by k_sweep
__device__ unsigned int g_dirty[NWORDS];   // 1 bit per Acc line; cleared by k_sweep

// Order-preserving float -> uint key. For any finite non-NaN f, fkey(f) > 0,
// so 0 is a valid "empty" sentinel for atomicMax accumulation.
__device__ __forceinline__ unsigned int fkey(float f) {
    unsigned int u = __float_as_uint(f);
    return (u & 0x80000000u) ? ~u : (u | 0x80000000u);
}
__device__ __forceinline__ float funkey(unsigned int k) {
    unsigned int u = (k & 0x80000000u) ? (k ^ 0x80000000u) : ~k;
    return __uint_as_float(u);
}

// Kernel A: one thread per (point, offset) candidate; hits do 4 atomics into
// the voxel's interleaved Acc plus one dirty-bit atomicOr per touched line.
// (Bit-identical to R9's proven scatter.)
__global__ void __launch_bounds__(TPB) k_scatter(
    const float4* __restrict__ cr,     // (B*N) x [cx, cy, cz, r]
    const float*  __restrict__ feat)   // (B*N) x 3
{
    int t  = blockIdx.x * TPB + threadIdx.x;   // candidate id
    int k  = t % KOFF;
    int pn = t / KOFF;                         // linear point id

    float4 c = __ldg(cr + pn);  // 125 consecutive threads share -> L1 broadcast

    int ox = k / 25 - 2;
    int oy = (k / 5) % 5 - 2;
    int oz = k % 5 - 2;

    // jnp.round == round-half-to-even == rn conversions
    int vx = __float2int_rn(c.x) + ox;
    int vy = __float2int_rn(c.y) + oy;
    int vz = __float2int_rn(c.z) + oz;

    // Exact IEEE ops, left-to-right sum, matching the reference (no FMA
    // contraction that could flip sphere-boundary membership).
    float dx = __fsub_rn((float)vx, c.x);
    float dy = __fsub_rn((float)vy, c.y);
    float dz = __fsub_rn((float)vz, c.z);
    float d2 = __fadd_rn(__fadd_rn(__fmul_rn(dx, dx), __fmul_rn(dy, dy)),
                         __fmul_rn(dz, dz));

    float rr = __fdiv_rn(rintf(__fmul_rn(c.w, 1000.0f)), 1000.0f);
    float r2 = __fmul_rn(rr, rr);

    bool ok = (d2 <= r2)
            && ((unsigned)vx < VOL) && ((unsigned)vy < VOL) && ((unsigned)vz < VOL);
    if (!ok) return;

    unsigned e = (unsigned)((pn >> 12) * (VOL * VOL * VOL)
                            + ((vx * VOL + vy) * VOL + vz));

    const float* fp = feat + (size_t)pn * 3;
    float f0 = __ldg(fp + 0);
    float f1 = __ldg(fp + 1);
    float f2 = __ldg(fp + 2);

    Acc* a = &g_acc[e];
    atomicMax(&a->maxk, fkey(f0));
    atomicMax(&a->mink, ~fkey(f1));     // min via max of complemented key
    atomicAdd(&a->cnt, 1u);
    atomicAdd(&a->sum, f2);

    unsigned line = e >> 3;             // 8 Acc per 128B line
    atomicOr(&g_dirty[line >> 5], 1u << (line & 31u));
}

// Kernel B: block handles WPB=8 bitmap words (8 x 256 voxels). Per iteration:
// word is block-uniform broadcast; clean voxel -> 12B of zeros; dirty line ->
// 16B Acc read (L2-hot), decode, 12B out, 16B Acc clean. Plain write-back
// stores park output in L2. After the loop, one barrier, then threads 0..7
// clear their words (all reads happened before the barrier; exclusive
// per-block ownership of words [b*8, b*8+8)).
__global__ void __launch_bounds__(TPB) k_sweep(float* __restrict__ out)
{
    unsigned b = blockIdx.x;
    unsigned dirtyflags = 0u;

#pragma unroll
    for (int it = 0; it < WPB; it++) {
        unsigned widx = b * WPB + it;
        unsigned w = g_dirty[widx];                // block-uniform broadcast
        dirtyflags |= (w != 0u ? 1u : 0u) << it;

        unsigned e = widx * 256 + threadIdx.x;     // voxel id
        size_t   o = (size_t)e * 3;                // 12B/thread, coalesced

        if (((w >> ((threadIdx.x >> 3) & 31u)) & 1u) == 0u) {  // clean line
            out[o + 0] = 0.0f;
            out[o + 1] = 0.0f;
            out[o + 2] = 0.0f;
        } else {
            uint4* ap = reinterpret_cast<uint4*>(g_acc) + e;   // lane-dense
            uint4 a = *ap;
            float v0 = 0.0f, v1 = 0.0f, v2 = 0.0f;
            if (a.z != 0u) {                       // cnt != 0
                v0 = funkey(a.x);
                v1 = funkey(~a.y);
                v2 = __fdiv_rn(__uint_as_float(a.w), (float)a.z);
                *ap = make_uint4(0u, 0u, 0u, 0u);  // self-clean for next call
            }
            out[o + 0] = v0;
            out[o + 1] = v1;
            out[o + 2] = v2;
        }
    }

    // All threads have consumed their words; clear the dirty ones.
    __syncthreads();
    if (threadIdx.x < WPB && ((dirtyflags >> threadIdx.x) & 1u))
        g_dirty[b * WPB + threadIdx.x] = 0u;
}

extern "C" void kernel_launch(void* const* d_in, const int* in_sizes, int n_in,
                              void* d_out, int out_size)
{
    const float4* cr   = (const float4*)d_in[0];  // coordinates_radii (B,N,4)
    const float*  feat = (const float*)d_in[1];   // features (B,N,3)
    float*        out  = (float*)d_out;           // (B,128,128,128,3) f32

    k_scatter<<<SCAT_BLOCKS, TPB>>>(cr, feat);
    k_sweep<<<SWEEP_BLOCKS, TPB>>>(out);
}